// round 1
// baseline (speedup 1.0000x reference)
#include <cuda_runtime.h>
#include <cstdint>

// Problem constants (fixed by the reference)
#define NN   24          // real nodes
#define EE   96          // directed edges
#define BB   4
#define CC   8
#define HH   96
#define WW   96
#define KK   4
#define HW    (HH*WW)            // 9216
#define CHW   (CC*HW)            // 73728
#define BCHW  (BB*CHW)           // 294912

#define TS    32                  // output tile side
#define INR   35                  // input tile rows/cols (TS + K - 1)
#define INSTR 36                  // padded stride for shared input
#define NTIL  9                   // (96/32)^2

// ---------------------------------------------------------------------------
// Device scratch (no allocations allowed)
// ---------------------------------------------------------------------------
__device__ int   g_off[NN + 1];
__device__ int   g_elist[EE];
__device__ float g_escale[EE];     // plasticity[e] / deg[dst[e]]
__device__ float g_postsum[NN];    // sum of sigmoid(future) per node

// ---------------------------------------------------------------------------
// Prep: per-dst edge lists, edge scales, zero postsum. 1 block, 128 threads.
// ---------------------------------------------------------------------------
__global__ void prep_kernel(const int* __restrict__ dst,
                            const float* __restrict__ plast) {
    __shared__ int cnt[NN];
    __shared__ int fill[NN];
    int t = threadIdx.x;
    if (t < NN) { cnt[t] = 0; g_postsum[t] = 0.0f; }
    __syncthreads();
    if (t < EE) atomicAdd(&cnt[dst[t]], 1);
    __syncthreads();
    if (t == 0) {
        int off = 0;
        for (int n = 0; n < NN; ++n) { g_off[n] = off; fill[n] = off; off += cnt[n]; }
        g_off[NN] = off;
    }
    __syncthreads();
    if (t < EE) {
        int d = dst[t];
        int pos = atomicAdd(&fill[d], 1);
        g_elist[pos] = t;
        int deg = cnt[d] > 0 ? cnt[d] : 1;
        g_escale[t] = plast[t] / (float)deg;
    }
}

// ---------------------------------------------------------------------------
// Main conv + aggregate kernel.
// grid = (9 tiles, B, N). 256 threads.
// Each block: loops over in-edges of node n, accumulates scaled conv into
// registers (8 cout x 4 pixels per thread), writes future once, and adds its
// tile's sum of sigmoid(future) into g_postsum[n].
// ---------------------------------------------------------------------------
__global__ __launch_bounds__(256, 3)
void conv_kernel(const float* __restrict__ states,
                 const float* __restrict__ weights,
                 const int* __restrict__ src,
                 float* __restrict__ out) {
    const int tile = blockIdx.x;
    const int ty0 = (tile / 3) * TS;
    const int tx0 = (tile % 3) * TS;
    const int b = blockIdx.y;
    const int n = blockIdx.z;

    __shared__ __align__(16) float s_w[CC * CC * KK * KK];   // 1024 floats
    __shared__ float s_in[CC * INR * INSTR];                 // 8*35*36 = 10080
    __shared__ float s_red[8];

    const int t = threadIdx.x;
    const int p0 = t * 4;             // first of 4 consecutive output pixels
    const int yl = p0 >> 5;           // local row   0..31
    const int xb = p0 & 31;           // local col   0,4,...,28

    float acc[CC][4];
#pragma unroll
    for (int co = 0; co < CC; ++co)
#pragma unroll
        for (int j = 0; j < 4; ++j) acc[co][j] = 0.0f;

    const int e_beg = g_off[n];
    const int e_end = g_off[n + 1];

    for (int ei = e_beg; ei < e_end; ++ei) {
        const int e = g_elist[ei];
        const int s = __ldg(&src[e]);
        const float esc = g_escale[e];

        __syncthreads();   // previous iteration's compute done before overwrite

        // weights for this edge: [co][ci][ky][kx] flat, 1024 floats
        const float* wg = weights + (size_t)e * (CC * CC * KK * KK);
        for (int i = t; i < CC * CC * KK * KK; i += 256) s_w[i] = wg[i];

        // input tile: sigmoid(states[src]) * escale, zero-padded
        const float* ig = states + ((size_t)s * BB + b) * CHW;
        for (int i = t; i < CC * INR * INR; i += 256) {
            int ci = i / (INR * INR);
            int r = (i - ci * INR * INR) / INR;
            int c = i - ci * INR * INR - r * INR;
            int gy = ty0 - 1 + r;
            int gx = tx0 - 1 + c;
            float v = 0.0f;
            if (gy >= 0 && gy < HH && gx >= 0 && gx < WW) {
                float z = ig[ci * HW + gy * WW + gx];
                v = esc / (1.0f + __expf(-z));
            }
            s_in[ci * (INR * INSTR) + r * INSTR + c] = v;
        }
        __syncthreads();

        // compute: sliding window over 4 consecutive x
#pragma unroll
        for (int ci = 0; ci < CC; ++ci) {
#pragma unroll
            for (int ky = 0; ky < KK; ++ky) {
                const float* rin = &s_in[ci * (INR * INSTR) + (yl + ky) * INSTR + xb];
                const float i0 = rin[0], i1 = rin[1], i2 = rin[2], i3 = rin[3];
                const float i4 = rin[4], i5 = rin[5], i6 = rin[6];
#pragma unroll
                for (int co = 0; co < CC; ++co) {
                    const float4 w4 = *reinterpret_cast<const float4*>(
                        &s_w[(((co << 3) + ci) << 4) + (ky << 2)]);
                    acc[co][0] += i0 * w4.x + i1 * w4.y + i2 * w4.z + i3 * w4.w;
                    acc[co][1] += i1 * w4.x + i2 * w4.y + i3 * w4.z + i4 * w4.w;
                    acc[co][2] += i2 * w4.x + i3 * w4.y + i4 * w4.z + i5 * w4.w;
                    acc[co][3] += i3 * w4.x + i4 * w4.y + i5 * w4.z + i6 * w4.w;
                }
            }
        }
    }

    // write future (each element written exactly once)
    {
        const int y = ty0 + yl;
        const int x = tx0 + xb;
        float* ob = out + (size_t)n * BCHW + (size_t)b * CHW + y * WW + x;
#pragma unroll
        for (int co = 0; co < CC; ++co) {
            float4 v = make_float4(acc[co][0], acc[co][1], acc[co][2], acc[co][3]);
            *reinterpret_cast<float4*>(ob + (size_t)co * HW) = v;
        }
    }

    // fused post-synaptic sum: sum of sigmoid(future) over this block's outputs
    float ls = 0.0f;
#pragma unroll
    for (int co = 0; co < CC; ++co)
#pragma unroll
        for (int j = 0; j < 4; ++j)
            ls += 1.0f / (1.0f + __expf(-acc[co][j]));
#pragma unroll
    for (int o = 16; o > 0; o >>= 1) ls += __shfl_down_sync(0xffffffffu, ls, o);
    if ((t & 31) == 0) s_red[t >> 5] = ls;
    __syncthreads();
    if (t == 0) {
        float sum = 0.0f;
#pragma unroll
        for (int w = 0; w < 8; ++w) sum += s_red[w];
        atomicAdd(&g_postsum[n], sum);
    }
}

// ---------------------------------------------------------------------------
// Plasticity epilogue. 1 block, 128 threads.
// ---------------------------------------------------------------------------
__global__ void plast_kernel(const float* __restrict__ plast,
                             const int* __restrict__ dst,
                             float* __restrict__ outp) {
    int e = threadIdx.x;
    if (e < EE) {
        float mean = g_postsum[dst[e]] * (1.0f / (float)BCHW);
        outp[e] = plast[e] + 0.1f * (mean - 0.5f);
    }
}

// ---------------------------------------------------------------------------
// Launch. Inputs (metadata order): states f32[25*B*C*H*W], weights f32[E*C*C*K*K],
// plasticity f32[E], src i32[E], dst i32[E]. Output: future f32[N*B*C*H*W] ++ plast f32[E].
// ---------------------------------------------------------------------------
extern "C" void kernel_launch(void* const* d_in, const int* in_sizes, int n_in,
                              void* d_out, int out_size) {
    const float* states  = (const float*)d_in[0];
    const float* weights = (const float*)d_in[1];
    const float* plast   = (const float*)d_in[2];
    const int*   src     = (const int*)d_in[3];
    const int*   dst     = (const int*)d_in[4];
    float* out = (float*)d_out;

    prep_kernel<<<1, 128>>>(dst, plast);

    dim3 grid(NTIL, BB, NN);
    conv_kernel<<<grid, 256>>>(states, weights, src, out);

    plast_kernel<<<1, 128>>>(plast, dst, out + (out_size - EE));
}

// round 2
// speedup vs baseline: 1.1483x; 1.1483x over previous
#include <cuda_runtime.h>
#include <cstdint>

// Problem constants
#define NN   24
#define EE   96
#define BB   4
#define CC   8
#define HH   96
#define WW   96
#define KK   4
#define HW    (HH*WW)            // 9216
#define CHW   (CC*HW)            // 73728
#define BCHW  (BB*CHW)           // 294912

#define TS    32
#define INR   35                  // TS + K - 1
#define INSTR 36                  // padded smem stride
#define NTIL  9

// Padded activation scratch: [25*B*C][100][100], border = 0, offset (+1,+1)
#define PH 100
#define PW 100
#define PLANE (PH*PW)             // 10000
#define NACT  (25*BB*CC*PLANE)    // 8,000,000 floats = 32MB

__device__ float g_act[NACT];
__device__ int   g_off[NN + 1];
__device__ int   g_elist[EE];
__device__ float g_escale[EE];
__device__ float g_postsum[NN];

// ---------------------------------------------------------------------------
// f32x2 packed helpers (PTX ISA 8.6+, sm_100+)
// ---------------------------------------------------------------------------
__device__ __forceinline__ unsigned long long pack2(float lo, float hi) {
    unsigned long long r;
    asm("mov.b64 %0, {%1,%2};" : "=l"(r) : "f"(lo), "f"(hi));
    return r;
}
__device__ __forceinline__ float2 unpack2(unsigned long long v) {
    float2 r;
    asm("mov.b64 {%0,%1}, %2;" : "=f"(r.x), "=f"(r.y) : "l"(v));
    return r;
}
__device__ __forceinline__ void fma2(unsigned long long& d,
                                     unsigned long long a,
                                     unsigned long long b) {
    asm("fma.rn.f32x2 %0, %1, %2, %0;" : "+l"(d) : "l"(a), "l"(b));
}

// ---------------------------------------------------------------------------
// Prep: per-dst edge lists + plasticity/deg scales, zero postsum.
// ---------------------------------------------------------------------------
__global__ void prep_kernel(const int* __restrict__ dst,
                            const float* __restrict__ plast) {
    __shared__ int cnt[NN];
    __shared__ int fill[NN];
    int t = threadIdx.x;
    if (t < NN) { cnt[t] = 0; g_postsum[t] = 0.0f; }
    __syncthreads();
    if (t < EE) atomicAdd(&cnt[dst[t]], 1);
    __syncthreads();
    if (t == 0) {
        int off = 0;
        for (int n = 0; n < NN; ++n) { g_off[n] = off; fill[n] = off; off += cnt[n]; }
        g_off[NN] = off;
    }
    __syncthreads();
    if (t < EE) {
        int d = dst[t];
        int pos = atomicAdd(&fill[d], 1);
        g_elist[pos] = t;
        int deg = cnt[d] > 0 ? cnt[d] : 1;
        g_escale[t] = plast[t] / (float)deg;
    }
}

// ---------------------------------------------------------------------------
// Activation precompute: sigmoid(states) into zero-padded scratch.
// grid covers all 8M padded elements.
// ---------------------------------------------------------------------------
__global__ void act_kernel(const float* __restrict__ states) {
    int idx = blockIdx.x * 256 + threadIdx.x;
    if (idx >= NACT) return;
    int plane = idx / PLANE;
    int rem = idx - plane * PLANE;
    int r = rem / PW;
    int c = rem - r * PW;
    int y = r - 1, x = c - 1;
    float v = 0.0f;
    if (y >= 0 && y < HH && x >= 0 && x < WW) {
        float z = states[(size_t)plane * HW + y * WW + x];
        v = 1.0f / (1.0f + __expf(-z));
    }
    g_act[idx] = v;
}

// ---------------------------------------------------------------------------
// Main conv + aggregate. grid = (9 tiles, B, N), 256 threads.
// f32x2 packed accumulation: each thread owns 4 consecutive x pixels x 8 cout
// as 2 packed accumulators per cout.
// ---------------------------------------------------------------------------
__global__ __launch_bounds__(256, 2)
void conv_kernel(const float* __restrict__ weights,
                 const int* __restrict__ src,
                 float* __restrict__ out) {
    const int tile = blockIdx.x;
    const int ty0 = (tile / 3) * TS;
    const int tx0 = (tile % 3) * TS;
    const int b = blockIdx.y;
    const int n = blockIdx.z;

    __shared__ __align__(16) float s_w2[2 * CC * CC * KK * KK];   // 2048 floats (w dup pairs)
    __shared__ __align__(16) float s_in[CC * INR * INSTR];        // 10080 floats
    __shared__ float s_red[8];

    const int t = threadIdx.x;
    const int p0 = t * 4;
    const int yl = p0 >> 5;           // 0..31
    const int xb = p0 & 31;           // 0,4,..,28

    unsigned long long acc01[CC], acc23[CC];
#pragma unroll
    for (int co = 0; co < CC; ++co) { acc01[co] = 0ULL; acc23[co] = 0ULL; }

    const int e_beg = g_off[n];
    const int e_end = g_off[n + 1];

    for (int ei = e_beg; ei < e_end; ++ei) {
        const int e = g_elist[ei];
        const int s = __ldg(&src[e]);
        const float esc = g_escale[e];

        __syncthreads();   // protect smem from previous iteration's readers

        // duplicated weight pairs, esc folded in: s_w2[2i]=s_w2[2i+1]=w[i]*esc
        const float* wg = weights + (size_t)e * (CC * CC * KK * KK);
        for (int i = t; i < CC * CC * KK * KK; i += 256) {
            float w = wg[i] * esc;
            reinterpret_cast<float2*>(s_w2)[i] = make_float2(w, w);
        }

        // input tile from padded activations: unconditional loads
        // s_in flat layout: ci*1260 + r*36 + c  (c in 0..35, last col harmless)
        const float* ap = g_act + (size_t)((s * BB + b) * CC) * PLANE
                        + ty0 * PW + tx0;
        for (int i = t; i < CC * INR * INSTR; i += 256) {
            int ci = i / (INR * INSTR);
            int rem = i - ci * (INR * INSTR);
            int r = rem / INSTR;
            s_in[i] = ap[ci * PLANE + r * (PW - INSTR) + rem];
        }
        __syncthreads();

#pragma unroll
        for (int ci = 0; ci < CC; ++ci) {
#pragma unroll
            for (int ky = 0; ky < KK; ++ky) {
                const float* rin = &s_in[ci * (INR * INSTR) + (yl + ky) * INSTR + xb];
                const float4 va = *reinterpret_cast<const float4*>(rin);
                const float4 vb = *reinterpret_cast<const float4*>(rin + 4);
                const unsigned long long pp0 = pack2(va.x, va.y);
                const unsigned long long pp1 = pack2(va.y, va.z);
                const unsigned long long pp2 = pack2(va.z, va.w);
                const unsigned long long pp3 = pack2(va.w, vb.x);
                const unsigned long long pp4 = pack2(vb.x, vb.y);
                const unsigned long long pp5 = pack2(vb.y, vb.z);
#pragma unroll
                for (int co = 0; co < CC; ++co) {
                    const int wb2 = 2 * ((((co << 3) + ci) << 4) + (ky << 2));
                    const ulonglong2 wa = *reinterpret_cast<const ulonglong2*>(&s_w2[wb2]);
                    const ulonglong2 wbv = *reinterpret_cast<const ulonglong2*>(&s_w2[wb2 + 4]);
                    fma2(acc01[co], pp0, wa.x);
                    fma2(acc01[co], pp1, wa.y);
                    fma2(acc01[co], pp2, wbv.x);
                    fma2(acc01[co], pp3, wbv.y);
                    fma2(acc23[co], pp2, wa.x);
                    fma2(acc23[co], pp3, wa.y);
                    fma2(acc23[co], pp4, wbv.x);
                    fma2(acc23[co], pp5, wbv.y);
                }
            }
        }
    }

    // write future
    {
        const int y = ty0 + yl;
        const int x = tx0 + xb;
        float* ob = out + (size_t)n * BCHW + (size_t)b * CHW + y * WW + x;
#pragma unroll
        for (int co = 0; co < CC; ++co) {
            float2 a = unpack2(acc01[co]);
            float2 c = unpack2(acc23[co]);
            *reinterpret_cast<float4*>(ob + (size_t)co * HW) =
                make_float4(a.x, a.y, c.x, c.y);
        }
    }

    // fused post-synaptic sigmoid sum
    float ls = 0.0f;
#pragma unroll
    for (int co = 0; co < CC; ++co) {
        float2 a = unpack2(acc01[co]);
        float2 c = unpack2(acc23[co]);
        ls += 1.0f / (1.0f + __expf(-a.x));
        ls += 1.0f / (1.0f + __expf(-a.y));
        ls += 1.0f / (1.0f + __expf(-c.x));
        ls += 1.0f / (1.0f + __expf(-c.y));
    }
#pragma unroll
    for (int o = 16; o > 0; o >>= 1) ls += __shfl_down_sync(0xffffffffu, ls, o);
    if ((t & 31) == 0) s_red[t >> 5] = ls;
    __syncthreads();
    if (t == 0) {
        float sum = 0.0f;
#pragma unroll
        for (int w = 0; w < 8; ++w) sum += s_red[w];
        atomicAdd(&g_postsum[n], sum);
    }
}

// ---------------------------------------------------------------------------
// Plasticity epilogue.
// ---------------------------------------------------------------------------
__global__ void plast_kernel(const float* __restrict__ plast,
                             const int* __restrict__ dst,
                             float* __restrict__ outp) {
    int e = threadIdx.x;
    if (e < EE) {
        float mean = g_postsum[dst[e]] * (1.0f / (float)BCHW);
        outp[e] = plast[e] + 0.1f * (mean - 0.5f);
    }
}

// ---------------------------------------------------------------------------
extern "C" void kernel_launch(void* const* d_in, const int* in_sizes, int n_in,
                              void* d_out, int out_size) {
    const float* states  = (const float*)d_in[0];
    const float* weights = (const float*)d_in[1];
    const float* plast   = (const float*)d_in[2];
    const int*   src     = (const int*)d_in[3];
    const int*   dst     = (const int*)d_in[4];
    float* out = (float*)d_out;

    prep_kernel<<<1, 128>>>(dst, plast);
    act_kernel<<<(NACT + 255) / 256, 256>>>(states);

    dim3 grid(NTIL, BB, NN);
    conv_kernel<<<grid, 256>>>(weights, src, out);

    plast_kernel<<<1, 128>>>(plast, dst, out + (out_size - EE));
}

// round 3
// speedup vs baseline: 2.5226x; 2.1968x over previous
#include <cuda_runtime.h>
#include <cstdint>

// Problem constants
#define NN   24
#define EE   96
#define BB   4
#define CC   8
#define HH   96
#define WW   96
#define KK   4
#define HW    (HH*WW)            // 9216
#define CHW   (CC*HW)            // 73728
#define BCHW  (BB*CHW)           // 294912

// Padded activation scratch: per (node<=24, b, ci) plane [100][100], zero border
#define PH 100
#define PW 100
#define PLANE (PH*PW)            // 10000
#define NACT  (25*BB*CC*PLANE)   // 8,000,000 floats

// Conv-MMA tiling
#define SEGPX  640               // padded pixels per block (40 m16 tiles)
#define NSEG   15                // 15*640 = 9600 = all q0 with y<96
#define TPW    5                 // m16 tiles per warp (8 warps)
#define WINF   944               // window floats needed per ci (639+303+1 -> 944, /4=236)
#define WIN4   236
#define WSTR   968               // ci stride in smem floats; 968 % 32 == 8 (bank spread)

__device__ __align__(16) float g_act[NACT];
__device__ int   g_off[NN + 1];
__device__ int   g_elist[EE];
__device__ float g_escale[EE];
__device__ float g_postsum[NN];

__device__ __forceinline__ uint32_t f2tf32(float v) {
    uint32_t r;
    asm("cvt.rna.tf32.f32 %0, %1;" : "=r"(r) : "f"(v));
    return r;
}

__device__ __forceinline__ void mma_tf32(float* d, uint32_t a0, uint32_t a1,
                                         uint32_t a2, uint32_t a3,
                                         uint32_t b0, uint32_t b1) {
    asm volatile(
        "mma.sync.aligned.m16n8k8.row.col.f32.tf32.tf32.f32 "
        "{%0,%1,%2,%3}, {%4,%5,%6,%7}, {%8,%9}, {%0,%1,%2,%3};"
        : "+f"(d[0]), "+f"(d[1]), "+f"(d[2]), "+f"(d[3])
        : "r"(a0), "r"(a1), "r"(a2), "r"(a3), "r"(b0), "r"(b1));
}

// ---------------------------------------------------------------------------
// act + prep fused. Block 0 additionally builds per-dst edge lists and scales.
// All blocks: sigmoid(states) -> tf32-rounded, zero-padded scratch.
// ---------------------------------------------------------------------------
__global__ void act_prep_kernel(const float* __restrict__ states,
                                const int* __restrict__ dst,
                                const float* __restrict__ plast) {
    int t = threadIdx.x;
    if (blockIdx.x == 0) {
        __shared__ int cnt[NN];
        __shared__ int fill[NN];
        if (t < NN) { cnt[t] = 0; g_postsum[t] = 0.0f; }
        __syncthreads();
        if (t < EE) atomicAdd(&cnt[dst[t]], 1);
        __syncthreads();
        if (t == 0) {
            int off = 0;
            for (int n = 0; n < NN; ++n) { g_off[n] = off; fill[n] = off; off += cnt[n]; }
            g_off[NN] = off;
        }
        __syncthreads();
        if (t < EE) {
            int d = dst[t];
            int pos = atomicAdd(&fill[d], 1);
            g_elist[pos] = t;
            int deg = cnt[d] > 0 ? cnt[d] : 1;
            g_escale[t] = plast[t] / (float)deg;
        }
    }
    int idx = blockIdx.x * 256 + t;
    if (idx >= NACT) return;
    int plane = idx / PLANE;
    int rem = idx - plane * PLANE;
    int r = rem / PW;
    int c = rem - r * PW;
    int y = r - 1, x = c - 1;
    float v = 0.0f;
    if (y >= 0 && y < HH && x >= 0 && x < WW) {
        float z = states[(size_t)plane * HW + y * WW + x];
        v = 1.0f / (1.0f + __expf(-z));
        v = __uint_as_float(f2tf32(v));   // pre-round to tf32
    }
    g_act[idx] = v;
}

// ---------------------------------------------------------------------------
// Conv via warp MMA (tf32). grid = (NSEG, B, N), 256 threads = 8 warps.
// Each warp: 5 m16n8k8 D-tiles (80 padded pixels x 8 cout), accumulated in
// registers over all in-edges of node n.
// ---------------------------------------------------------------------------
__global__ __launch_bounds__(256, 2)
void conv_mma_kernel(const float* __restrict__ weights,
                     const int* __restrict__ src,
                     float* __restrict__ out) {
    const int seg = blockIdx.x;
    const int b = blockIdx.y;
    const int n = blockIdx.z;
    const int qbase = seg * SEGPX;

    __shared__ __align__(16) float s_win[CC * WSTR];   // 30976 B
    __shared__ float s_red[8];

    const int t = threadIdx.x;
    const int w = t >> 5;
    const int l = t & 31;
    const int gid = l >> 2;      // 0..7  (fragment row group)
    const int tig = l & 3;       // 0..3  (fragment col group)

    float d[TPW][4];
#pragma unroll
    for (int u = 0; u < TPW; ++u)
#pragma unroll
        for (int j = 0; j < 4; ++j) d[u][j] = 0.0f;

    const int ebeg = g_off[n];
    const int eend = g_off[n + 1];

    for (int ei = ebeg; ei < eend; ++ei) {
        const int e = g_elist[ei];
        const int s = __ldg(&src[e]);
        const float esc = g_escale[e];

        // B fragments: b0 -> (ci=tig, co=gid), b1 -> (ci=tig+4, co=gid), all 16 (ky,kx)
        uint32_t b0r[16], b1r[16];
        {
            const float* wg = weights + (size_t)e * (CC * CC * KK * KK);
            const float4* p0 = reinterpret_cast<const float4*>(wg + ((gid * CC + tig) << 4));
            const float4* p1 = reinterpret_cast<const float4*>(wg + ((gid * CC + tig + 4) << 4));
#pragma unroll
            for (int k4 = 0; k4 < 4; ++k4) {
                float4 v0 = p0[k4];
                float4 v1 = p1[k4];
                b0r[k4 * 4 + 0] = f2tf32(v0.x * esc);
                b0r[k4 * 4 + 1] = f2tf32(v0.y * esc);
                b0r[k4 * 4 + 2] = f2tf32(v0.z * esc);
                b0r[k4 * 4 + 3] = f2tf32(v0.w * esc);
                b1r[k4 * 4 + 0] = f2tf32(v1.x * esc);
                b1r[k4 * 4 + 1] = f2tf32(v1.y * esc);
                b1r[k4 * 4 + 2] = f2tf32(v1.z * esc);
                b1r[k4 * 4 + 3] = f2tf32(v1.w * esc);
            }
        }

        __syncthreads();   // previous iteration's readers done
        // stage activation window: 8 planes x 944 floats (in-bounds by construction)
        {
            const float* ap = g_act + (size_t)((s * BB + b) * CC) * PLANE + qbase;
            if (t < WIN4) {
#pragma unroll
                for (int ci = 0; ci < CC; ++ci) {
                    reinterpret_cast<float4*>(s_win + ci * WSTR)[t] =
                        reinterpret_cast<const float4*>(ap + (size_t)ci * PLANE)[t];
                }
            }
        }
        __syncthreads();

#pragma unroll
        for (int u = 0; u < TPW; ++u) {
            const int lq = (w * TPW + u) * 16;
            const float* base0 = s_win + tig * WSTR + lq + gid;
#pragma unroll
            for (int ky = 0; ky < KK; ++ky) {
#pragma unroll
                for (int kx = 0; kx < KK; ++kx) {
                    const int o = ky * PW + kx;
                    uint32_t a0 = __float_as_uint(base0[o]);
                    uint32_t a1 = __float_as_uint(base0[o + 8]);
                    uint32_t a2 = __float_as_uint(base0[o + 4 * WSTR]);
                    uint32_t a3 = __float_as_uint(base0[o + 4 * WSTR + 8]);
                    mma_tf32(d[u], a0, a1, a2, a3, b0r[ky * 4 + kx], b1r[ky * 4 + kx]);
                }
            }
        }
    }

    // Epilogue: scatter valid outputs (x<96), fused sigmoid sum for plasticity.
    float ls = 0.0f;
    const int co0 = tig * 2;
    float* outn = out + (size_t)((n * BB + b) * CC) * HW;
#pragma unroll
    for (int u = 0; u < TPW; ++u) {
        const int lq = qbase + (w * TPW + u) * 16;
#pragma unroll
        for (int h = 0; h < 2; ++h) {
            const int q = lq + gid + h * 8;
            const int y = q / PW;
            const int x = q - y * PW;
            if (x < WW) {
                float v0 = d[u][h * 2 + 0];
                float v1 = d[u][h * 2 + 1];
                float* ob = outn + y * WW + x;
                ob[(size_t)co0 * HW] = v0;
                ob[(size_t)(co0 + 1) * HW] = v1;
                ls += 1.0f / (1.0f + __expf(-v0));
                ls += 1.0f / (1.0f + __expf(-v1));
            }
        }
    }
#pragma unroll
    for (int o = 16; o > 0; o >>= 1) ls += __shfl_down_sync(0xffffffffu, ls, o);
    if (l == 0) s_red[w] = ls;
    __syncthreads();
    if (t == 0) {
        float sum = 0.0f;
#pragma unroll
        for (int i = 0; i < 8; ++i) sum += s_red[i];
        atomicAdd(&g_postsum[n], sum);
    }
}

// ---------------------------------------------------------------------------
// Plasticity epilogue.
// ---------------------------------------------------------------------------
__global__ void plast_kernel(const float* __restrict__ plast,
                             const int* __restrict__ dst,
                             float* __restrict__ outp) {
    int e = threadIdx.x;
    if (e < EE) {
        float mean = g_postsum[dst[e]] * (1.0f / (float)BCHW);
        outp[e] = plast[e] + 0.1f * (mean - 0.5f);
    }
}

// ---------------------------------------------------------------------------
extern "C" void kernel_launch(void* const* d_in, const int* in_sizes, int n_in,
                              void* d_out, int out_size) {
    const float* states  = (const float*)d_in[0];
    const float* weights = (const float*)d_in[1];
    const float* plast   = (const float*)d_in[2];
    const int*   src     = (const int*)d_in[3];
    const int*   dst     = (const int*)d_in[4];
    float* out = (float*)d_out;

    act_prep_kernel<<<(NACT + 255) / 256, 256>>>(states, dst, plast);

    dim3 grid(NSEG, BB, NN);
    conv_mma_kernel<<<grid, 256>>>(weights, src, out);

    plast_kernel<<<1, 128>>>(plast, dst, out + (out_size - EE));
}

// round 4
// speedup vs baseline: 2.7822x; 1.1029x over previous
#include <cuda_runtime.h>
#include <cstdint>

// Problem constants
#define NN   24
#define EE   96
#define BB   4
#define CC   8
#define HH   96
#define WW   96
#define KK   4
#define HW    (HH*WW)            // 9216
#define CHW   (CC*HW)            // 73728
#define BCHW  (BB*CHW)           // 294912

// Padded activation scratch: per (node<=24, b, ci) plane [100][100], zero border.
// Borders are NEVER written: __device__ globals are zero-initialized and the
// act kernel only writes the 96x96 interior (deterministic across replays).
#define PH 100
#define PW 100
#define PLANE (PH*PW)            // 10000
#define NACT  (25*BB*CC*PLANE)

// Conv-MMA tiling
#define SEGPX  640               // padded pixels per block (40 m16 tiles)
#define NSEG   15                // 15*640 = 9600 = all q with y<96
#define TPW    5                 // m16 tiles per warp (8 warps)
#define WIN4   236               // float4s per ci plane window (944 floats)
#define WSTR   968               // ci stride in smem floats (bank spread: 968%32==8)
#define BUFF   (CC*WSTR)         // 7744 floats per buffer
#define NBLK   (NSEG*BB*NN)      // 1440 conv blocks

__device__ __align__(16) float g_act[NACT];
__device__ int   g_off[NN + 1];
__device__ int   g_elist[EE];
__device__ float g_escale[EE];
__device__ float g_postsum[NN];
__device__ unsigned int g_done;

__device__ __forceinline__ uint32_t f2tf32(float v) {
    uint32_t r;
    asm("cvt.rna.tf32.f32 %0, %1;" : "=r"(r) : "f"(v));
    return r;
}

__device__ __forceinline__ void mma_tf32(float* d, uint32_t a0, uint32_t a1,
                                         uint32_t a2, uint32_t a3,
                                         uint32_t b0, uint32_t b1) {
    asm volatile(
        "mma.sync.aligned.m16n8k8.row.col.f32.tf32.tf32.f32 "
        "{%0,%1,%2,%3}, {%4,%5,%6,%7}, {%8,%9}, {%0,%1,%2,%3};"
        : "+f"(d[0]), "+f"(d[1]), "+f"(d[2]), "+f"(d[3])
        : "r"(a0), "r"(a1), "r"(a2), "r"(a3), "r"(b0), "r"(b1));
}

__device__ __forceinline__ void cpa16(uint32_t dst, const void* src) {
    asm volatile("cp.async.cg.shared.global [%0], [%1], 16;"
                 :: "r"(dst), "l"(src));
}
__device__ __forceinline__ uint32_t smem_u32(const void* p) {
    uint32_t a;
    asm("{ .reg .u64 t; cvta.to.shared.u64 t, %1; cvt.u32.u64 %0, t; }"
        : "=r"(a) : "l"(p));
    return a;
}

// ---------------------------------------------------------------------------
// Activation precompute (+ prep in block (0,0)).
// grid = (9, 800). Each thread: 1 float4 read, 4 sigmoids, 4 scalar writes.
// ---------------------------------------------------------------------------
__global__ __launch_bounds__(256)
void act_prep_kernel(const float* __restrict__ states,
                     const int* __restrict__ dst,
                     const float* __restrict__ plast) {
    const int t = threadIdx.x;
    if (blockIdx.x == 0 && blockIdx.y == 0) {
        __shared__ int cnt[NN];
        __shared__ int fill[NN];
        if (t < NN) { cnt[t] = 0; g_postsum[t] = 0.0f; }
        __syncthreads();
        if (t < EE) atomicAdd(&cnt[dst[t]], 1);
        __syncthreads();
        if (t == 0) {
            int off = 0;
            for (int n = 0; n < NN; ++n) { g_off[n] = off; fill[n] = off; off += cnt[n]; }
            g_off[NN] = off;
        }
        __syncthreads();
        if (t < EE) {
            int d = dst[t];
            int pos = atomicAdd(&fill[d], 1);
            g_elist[pos] = t;
            int deg = cnt[d] > 0 ? cnt[d] : 1;
            g_escale[t] = plast[t] / (float)deg;
        }
    }
    const int plane = blockIdx.y;                 // 0..799
    const int idx4 = blockIdx.x * 256 + t;        // 0..2303 exactly (9*256)
    const int r = idx4 / 24;                      // row 0..95 (const-div)
    const int c4 = idx4 - r * 24;                 // float4 col 0..23

    const float4 z4 = *reinterpret_cast<const float4*>(
        states + (size_t)plane * HW + r * WW + c4 * 4);

    float v0 = __uint_as_float(f2tf32(1.0f / (1.0f + __expf(-z4.x))));
    float v1 = __uint_as_float(f2tf32(1.0f / (1.0f + __expf(-z4.y))));
    float v2 = __uint_as_float(f2tf32(1.0f / (1.0f + __expf(-z4.z))));
    float v3 = __uint_as_float(f2tf32(1.0f / (1.0f + __expf(-z4.w))));

    float* op = g_act + (size_t)plane * PLANE + (r + 1) * PW + 1 + c4 * 4;
    op[0] = v0; op[1] = v1; op[2] = v2; op[3] = v3;
}

// ---------------------------------------------------------------------------
// Conv via warp MMA (tf32), cp.async double-buffered window, fused plasticity.
// grid = (NSEG, B, N), 256 threads = 8 warps. Dynamic smem: 2 * BUFF floats.
// ---------------------------------------------------------------------------
extern __shared__ float s_dyn[];

__global__ __launch_bounds__(256, 2)
void conv_mma_kernel(const float* __restrict__ weights,
                     const int* __restrict__ src,
                     const float* __restrict__ plast,
                     const int* __restrict__ dst,
                     float* __restrict__ out,
                     float* __restrict__ outp) {
    const int seg = blockIdx.x;
    const int b = blockIdx.y;
    const int n = blockIdx.z;
    const int qbase = seg * SEGPX;

    __shared__ float s_red[8];
    __shared__ int s_last;
    float* s_win = s_dyn;                          // [2][BUFF]
    const uint32_t s_win_u32 = smem_u32(s_win);

    const int t = threadIdx.x;
    const int w = t >> 5;
    const int l = t & 31;
    const int gid = l >> 2;
    const int tig = l & 3;

    float d[TPW][4];
#pragma unroll
    for (int u = 0; u < TPW; ++u)
#pragma unroll
        for (int j = 0; j < 4; ++j) d[u][j] = 0.0f;

    const int ebeg = g_off[n];
    const int eend = g_off[n + 1];

    // ---- prefetch window for first edge into buffer 0
    {
        const int s = __ldg(&src[g_elist[ebeg]]);
        const float4* ap = reinterpret_cast<const float4*>(
            g_act + (size_t)((s * BB + b) * CC) * PLANE + qbase);
        if (t < WIN4) {
#pragma unroll
            for (int ci = 0; ci < CC; ++ci)
                cpa16(s_win_u32 + (ci * WSTR + t * 4) * 4, ap + ci * (PLANE / 4) + t);
        }
        asm volatile("cp.async.commit_group;");
    }

    for (int ei = ebeg; ei < eend; ++ei) {
        const int p = (ei - ebeg) & 1;
        const int e = g_elist[ei];
        const float esc = g_escale[e];

        // B fragments (overlaps the async window copy)
        uint32_t b0r[16], b1r[16];
        {
            const float* wg = weights + (size_t)e * (CC * CC * KK * KK);
            const float4* p0 = reinterpret_cast<const float4*>(wg + ((gid * CC + tig) << 4));
            const float4* p1 = reinterpret_cast<const float4*>(wg + ((gid * CC + tig + 4) << 4));
#pragma unroll
            for (int k4 = 0; k4 < 4; ++k4) {
                float4 v0 = p0[k4];
                float4 v1 = p1[k4];
                b0r[k4 * 4 + 0] = f2tf32(v0.x * esc);
                b0r[k4 * 4 + 1] = f2tf32(v0.y * esc);
                b0r[k4 * 4 + 2] = f2tf32(v0.z * esc);
                b0r[k4 * 4 + 3] = f2tf32(v0.w * esc);
                b1r[k4 * 4 + 0] = f2tf32(v1.x * esc);
                b1r[k4 * 4 + 1] = f2tf32(v1.y * esc);
                b1r[k4 * 4 + 2] = f2tf32(v1.z * esc);
                b1r[k4 * 4 + 3] = f2tf32(v1.w * esc);
            }
        }

        asm volatile("cp.async.wait_group 0;");
        __syncthreads();               // window p ready; prev compute on 1-p done

        // prefetch next edge's window into the other buffer
        if (ei + 1 < eend) {
            const int s2 = __ldg(&src[g_elist[ei + 1]]);
            const float4* ap2 = reinterpret_cast<const float4*>(
                g_act + (size_t)((s2 * BB + b) * CC) * PLANE + qbase);
            const uint32_t dbase = s_win_u32 + (1 - p) * (BUFF * 4);
            if (t < WIN4) {
#pragma unroll
                for (int ci = 0; ci < CC; ++ci)
                    cpa16(dbase + (ci * WSTR + t * 4) * 4, ap2 + ci * (PLANE / 4) + t);
            }
            asm volatile("cp.async.commit_group;");
        }

        // compute on buffer p
        const float* buf = s_win + p * BUFF;
#pragma unroll
        for (int u = 0; u < TPW; ++u) {
            const int lq = (w * TPW + u) * 16;
            const float* base0 = buf + tig * WSTR + lq + gid;
#pragma unroll
            for (int ky = 0; ky < KK; ++ky) {
#pragma unroll
                for (int kx = 0; kx < KK; ++kx) {
                    const int o = ky * PW + kx;
                    uint32_t a0 = __float_as_uint(base0[o]);
                    uint32_t a1 = __float_as_uint(base0[o + 8]);
                    uint32_t a2 = __float_as_uint(base0[o + 4 * WSTR]);
                    uint32_t a3 = __float_as_uint(base0[o + 4 * WSTR + 8]);
                    mma_tf32(d[u], a0, a1, a2, a3, b0r[ky * 4 + kx], b1r[ky * 4 + kx]);
                }
            }
        }
    }

    // Epilogue: store future, fused sigmoid sum
    float ls = 0.0f;
    const int co0 = tig * 2;
    float* outn = out + (size_t)((n * BB + b) * CC) * HW;
#pragma unroll
    for (int u = 0; u < TPW; ++u) {
        const int lq = qbase + (w * TPW + u) * 16;
#pragma unroll
        for (int h = 0; h < 2; ++h) {
            const int q = lq + gid + h * 8;
            const int y = q / PW;
            const int x = q - y * PW;
            if (x < WW) {
                float v0 = d[u][h * 2 + 0];
                float v1 = d[u][h * 2 + 1];
                float* ob = outn + y * WW + x;
                ob[(size_t)co0 * HW] = v0;
                ob[(size_t)(co0 + 1) * HW] = v1;
                ls += 1.0f / (1.0f + __expf(-v0));
                ls += 1.0f / (1.0f + __expf(-v1));
            }
        }
    }
#pragma unroll
    for (int o = 16; o > 0; o >>= 1) ls += __shfl_down_sync(0xffffffffu, ls, o);
    if (l == 0) s_red[w] = ls;
    __syncthreads();
    if (t == 0) {
        float sum = 0.0f;
#pragma unroll
        for (int i = 0; i < 8; ++i) sum += s_red[i];
        atomicAdd(&g_postsum[n], sum);
        __threadfence();
        unsigned prev = atomicAdd(&g_done, 1u);
        s_last = (prev == NBLK - 1) ? 1 : 0;
        if (s_last) g_done = 0;        // all blocks already arrived; safe reset
    }
    __syncthreads();
    if (s_last && t < EE) {            // fused plasticity epilogue (last block)
        float mean = g_postsum[dst[t]] * (1.0f / (float)BCHW);
        outp[t] = plast[t] + 0.1f * (mean - 0.5f);
    }
}

// ---------------------------------------------------------------------------
extern "C" void kernel_launch(void* const* d_in, const int* in_sizes, int n_in,
                              void* d_out, int out_size) {
    const float* states  = (const float*)d_in[0];
    const float* weights = (const float*)d_in[1];
    const float* plast   = (const float*)d_in[2];
    const int*   src     = (const int*)d_in[3];
    const int*   dst     = (const int*)d_in[4];
    float* out = (float*)d_out;

    dim3 agrid(9, 25 * BB * CC);   // 9 chunks x 800 planes
    act_prep_kernel<<<agrid, 256>>>(states, dst, plast);

    static int smem_set = 0;
    const int smem_bytes = 2 * BUFF * 4;     // 61952
    if (!smem_set) {
        cudaFuncSetAttribute(conv_mma_kernel,
                             cudaFuncAttributeMaxDynamicSharedMemorySize,
                             smem_bytes);
        smem_set = 1;
    }
    dim3 grid(NSEG, BB, NN);
    conv_mma_kernel<<<grid, 256, smem_bytes>>>(weights, src, plast, dst, out,
                                               out + (out_size - EE));
}